// round 15
// baseline (speedup 1.0000x reference)
#include <cuda_runtime.h>
#include <cuda_bf16.h>
#include <cstdint>

#define BROWS 4096
#define DIN   512
#define DH    256
#define DG    128
#define NHEAD 8
#define NCAT  3328   // 256 (h-branch) + 2048 (z1) + 1024 (z2)

// fp32 GEMM result
__device__ float g_scratch[(size_t)BROWS * NCAT];
// h buffer for fuse2
__device__ float g_h[(size_t)BROWS * DH];
// bf16 split operands for the big GEMM
__device__ __nv_bfloat16 g_xh[(size_t)BROWS * DIN];
__device__ __nv_bfloat16 g_xl[(size_t)BROWS * DIN];
__device__ __nv_bfloat16 g_wth[(size_t)NCAT * DIN];
__device__ __nv_bfloat16 g_wtl[(size_t)NCAT * DIN];

__device__ __forceinline__ uint32_t smem_u32(const void* p) {
    uint32_t a;
    asm("{ .reg .u64 t; cvta.to.shared.u64 t, %1; cvt.u32.u64 %0, t; }" : "=r"(a) : "l"(p));
    return a;
}
__device__ __forceinline__ float tanh_fast(float x) {
    float r;
    asm("tanh.approx.f32 %0, %1;" : "=f"(r) : "f"(x));
    return r;
}

#define LDSM_X4(r0, r1, r2, r3, addr) \
    asm volatile("ldmatrix.sync.aligned.m8n8.x4.shared.b16 {%0,%1,%2,%3}, [%4];" \
                 : "=r"(r0), "=r"(r1), "=r"(r2), "=r"(r3) : "r"(addr))
#define LDSM_X2(r0, r1, addr) \
    asm volatile("ldmatrix.sync.aligned.m8n8.x2.shared.b16 {%0,%1}, [%2];" \
                 : "=r"(r0), "=r"(r1) : "r"(addr))

#define MMA_BF16(d, a, b) \
    asm volatile("mma.sync.aligned.m16n8k16.row.col.f32.bf16.bf16.f32 " \
                 "{%0,%1,%2,%3}, {%4,%5,%6,%7}, {%8,%9}, {%0,%1,%2,%3};" \
                 : "+f"((d)[0]), "+f"((d)[1]), "+f"((d)[2]), "+f"((d)[3]) \
                 : "r"((a)[0]), "r"((a)[1]), "r"((a)[2]), "r"((a)[3]), \
                   "r"((b)[0]), "r"((b)[1]))

#define MMA8(d, a, b) \
    asm volatile("mma.sync.aligned.m16n8k8.row.col.f32.bf16.bf16.f32 " \
                 "{%0,%1,%2,%3}, {%4,%5}, {%6}, {%0,%1,%2,%3};" \
                 : "+f"((d)[0]), "+f"((d)[1]), "+f"((d)[2]), "+f"((d)[3]) \
                 : "r"((a)[0]), "r"((a)[1]), "r"((b)))

// ---------------------------------------------------------------------------
// Convert X -> bf16 hi/lo
// ---------------------------------------------------------------------------
__global__ void convert_x_kernel(const float* __restrict__ X) {
    size_t i = ((size_t)blockIdx.x * blockDim.x + threadIdx.x) * 4;
    float4 v = *(const float4*)(X + i);
    __nv_bfloat16 h0 = __float2bfloat16(v.x), h1 = __float2bfloat16(v.y);
    __nv_bfloat16 h2 = __float2bfloat16(v.z), h3 = __float2bfloat16(v.w);
    __nv_bfloat162 hp0 = {h0, h1}, hp1 = {h2, h3};
    *(__nv_bfloat162*)(g_xh + i)     = hp0;
    *(__nv_bfloat162*)(g_xh + i + 2) = hp1;
    __nv_bfloat162 lp0 = {__float2bfloat16(v.x - __bfloat162float(h0)),
                          __float2bfloat16(v.y - __bfloat162float(h1))};
    __nv_bfloat162 lp1 = {__float2bfloat16(v.z - __bfloat162float(h2)),
                          __float2bfloat16(v.w - __bfloat162float(h3))};
    *(__nv_bfloat162*)(g_xl + i)     = lp0;
    *(__nv_bfloat162*)(g_xl + i + 2) = lp1;
}

// ---------------------------------------------------------------------------
// Transpose-convert [Wh|Wz1|Wz2] -> WT [3328, 512] bf16 hi/lo
// ---------------------------------------------------------------------------
__global__ __launch_bounds__(1024)
void convert_w_kernel(const float* __restrict__ Wh,
                      const float* __restrict__ Wz1,
                      const float* __restrict__ Wz2) {
    __shared__ float tile[32][33];
    const int n0 = blockIdx.x * 32;
    const int k0 = blockIdx.y * 32;
    const int tx = threadIdx.x & 31;
    const int ty = threadIdx.x >> 5;

    int n = n0 + tx, k = k0 + ty;
    float v;
    if (n < 256)       v = Wh [(size_t)k * 256  + n];
    else if (n < 2304) v = Wz1[(size_t)k * 2048 + (n - 256)];
    else               v = Wz2[(size_t)k * 1024 + (n - 2304)];
    tile[ty][tx] = v;
    __syncthreads();

    float w = tile[tx][ty];
    __nv_bfloat16 hi = __float2bfloat16(w);
    __nv_bfloat16 lo = __float2bfloat16(w - __bfloat162float(hi));
    size_t o = (size_t)(n0 + ty) * DIN + k0 + tx;
    g_wth[o] = hi;
    g_wtl[o] = lo;
}

// ---------------------------------------------------------------------------
// mma.sync bf16x3 GEMM: C[4096,3328] = X @ Wcat (unchanged from R11)
// ---------------------------------------------------------------------------
#define KSTR 40

__global__ __launch_bounds__(256, 2)
void gemm_mma_kernel() {
    __shared__ __nv_bfloat16 sAh[128 * KSTR];
    __shared__ __nv_bfloat16 sAl[128 * KSTR];
    __shared__ __nv_bfloat16 sBh[128 * KSTR];
    __shared__ __nv_bfloat16 sBl[128 * KSTR];

    const int tid  = threadIdx.x;
    const int wid  = tid >> 5;
    const int lane = tid & 31;
    const int n0 = blockIdx.x * 128;
    const int m0 = blockIdx.y * 128;
    const int wm = wid & 1;
    const int wn = wid >> 1;

    const int grow = tid >> 1;
    const int gc   = (tid & 1) * 16;
    const size_t aoff = (size_t)(m0 + grow) * DIN + gc;
    const size_t boff = (size_t)(n0 + grow) * DIN + gc;
    const int soff = grow * KSTR + gc;

    const uint32_t uAh = smem_u32(sAh), uAl = smem_u32(sAl);
    const uint32_t uBh = smem_u32(sBh), uBl = smem_u32(sBl);

    const int arow = wm * 64 + (lane & 15);
    const int acol = (lane >> 4) * 8;
    const int brow = wn * 32 + (lane & 7) + ((lane & 16) >> 1);
    const int bcol = (lane & 8);

    float acc[4][4][4];
    #pragma unroll
    for (int mi = 0; mi < 4; mi++)
        #pragma unroll
        for (int ni = 0; ni < 4; ni++)
            #pragma unroll
            for (int q = 0; q < 4; q++) acc[mi][ni][q] = 0.f;

    #pragma unroll 1
    for (int kc = 0; kc < 16; kc++) {
        const int kb = kc * 32;
        int4 vah0 = *(const int4*)(g_xh  + aoff + kb);
        int4 vah1 = *(const int4*)(g_xh  + aoff + kb + 8);
        int4 val0 = *(const int4*)(g_xl  + aoff + kb);
        int4 val1 = *(const int4*)(g_xl  + aoff + kb + 8);
        int4 vbh0 = *(const int4*)(g_wth + boff + kb);
        int4 vbh1 = *(const int4*)(g_wth + boff + kb + 8);
        int4 vbl0 = *(const int4*)(g_wtl + boff + kb);
        int4 vbl1 = *(const int4*)(g_wtl + boff + kb + 8);
        __syncthreads();
        *(int4*)(sAh + soff) = vah0;  *(int4*)(sAh + soff + 8) = vah1;
        *(int4*)(sAl + soff) = val0;  *(int4*)(sAl + soff + 8) = val1;
        *(int4*)(sBh + soff) = vbh0;  *(int4*)(sBh + soff + 8) = vbh1;
        *(int4*)(sBl + soff) = vbl0;  *(int4*)(sBl + soff + 8) = vbl1;
        __syncthreads();

        #pragma unroll
        for (int ks = 0; ks < 2; ks++) {
            const int kk = ks * 16;
            uint32_t a[4][4], b1[4][2], b2[4][2];

            #pragma unroll
            for (int mi = 0; mi < 4; mi++) {
                uint32_t ad = uAh + 2u * (uint32_t)((arow + mi * 16) * KSTR + kk + acol);
                LDSM_X4(a[mi][0], a[mi][1], a[mi][2], a[mi][3], ad);
            }
            #pragma unroll
            for (int p = 0; p < 2; p++) {
                uint32_t bd = uBh + 2u * (uint32_t)((brow + p * 16) * KSTR + kk + bcol);
                LDSM_X4(b1[p*2][0], b1[p*2][1], b1[p*2+1][0], b1[p*2+1][1], bd);
            }
            #pragma unroll
            for (int mi = 0; mi < 4; mi++)
                #pragma unroll
                for (int ni = 0; ni < 4; ni++)
                    MMA_BF16(acc[mi][ni], a[mi], b1[ni]);

            #pragma unroll
            for (int p = 0; p < 2; p++) {
                uint32_t bd = uBl + 2u * (uint32_t)((brow + p * 16) * KSTR + kk + bcol);
                LDSM_X4(b2[p*2][0], b2[p*2][1], b2[p*2+1][0], b2[p*2+1][1], bd);
            }
            #pragma unroll
            for (int mi = 0; mi < 4; mi++)
                #pragma unroll
                for (int ni = 0; ni < 4; ni++)
                    MMA_BF16(acc[mi][ni], a[mi], b2[ni]);

            #pragma unroll
            for (int mi = 0; mi < 4; mi++) {
                uint32_t ad = uAl + 2u * (uint32_t)((arow + mi * 16) * KSTR + kk + acol);
                LDSM_X4(a[mi][0], a[mi][1], a[mi][2], a[mi][3], ad);
            }
            #pragma unroll
            for (int mi = 0; mi < 4; mi++)
                #pragma unroll
                for (int ni = 0; ni < 4; ni++)
                    MMA_BF16(acc[mi][ni], a[mi], b1[ni]);
        }
    }

    const int erow = m0 + wm * 64 + (lane >> 2);
    const int ecol = n0 + wn * 32 + (lane & 3) * 2;
    #pragma unroll
    for (int mi = 0; mi < 4; mi++)
        #pragma unroll
        for (int ni = 0; ni < 4; ni++) {
            float* d0 = g_scratch + (size_t)(erow + mi * 16) * NCAT + ecol + ni * 8;
            float* d1 = d0 + 8 * NCAT;
            *(float2*)d0 = make_float2(acc[mi][ni][0], acc[mi][ni][1]);
            *(float2*)d1 = make_float2(acc[mi][ni][2], acc[mi][ni][3]);
        }
}

// ---------------------------------------------------------------------------
// LN branch: h = LN(relu(scratch[:,0:256] + bh)) -> out and g_h
// ---------------------------------------------------------------------------
__global__ __launch_bounds__(256)
void ln_kernel(const float* __restrict__ bh,
               const float* __restrict__ ln_scale,
               const float* __restrict__ ln_bias,
               float* __restrict__ out)
{
    const int b    = blockIdx.x;
    const int tid  = threadIdx.x;
    const int lane = tid & 31;
    const int wid  = tid >> 5;
    __shared__ float red[2][8];

    float v = fmaxf(g_scratch[(size_t)b * NCAT + tid] + bh[tid], 0.f);
    float s = v, q = v * v;
    #pragma unroll
    for (int o = 16; o; o >>= 1) {
        s += __shfl_xor_sync(0xffffffffu, s, o);
        q += __shfl_xor_sync(0xffffffffu, q, o);
    }
    if (lane == 0) { red[0][wid] = s; red[1][wid] = q; }
    __syncthreads();
    float ts = 0.f, tq = 0.f;
    #pragma unroll
    for (int i = 0; i < 8; i++) { ts += red[0][i]; tq += red[1][i]; }
    const float mu  = ts * (1.f / 256.f);
    const float var = tq * (1.f / 256.f) - mu * mu;
    const float inv = rsqrtf(var + 1e-6f);
    const float hv  = (v - mu) * inv * ln_scale[tid] + ln_bias[tid];
    out[(size_t)b * DH + tid] = hv;
    g_h[(size_t)b * DH + tid] = hv;
}

// ---------------------------------------------------------------------------
// fuse2: per (row, 64-g half) block. w = z2^T z1 via m16n8k8 bf16x3 HMMA,
// stats via quad shuffles + smem, tanh via MUFU, y = w~ . h.
// Warp layout: 8 warps = 4 g-strips (16 g) x 2 d-halves (128 d).
// ---------------------------------------------------------------------------
__global__ __launch_bounds__(256, 2)
void fuse2_kernel(float* __restrict__ out)
{
    const int row  = blockIdx.x >> 1;
    const int g0   = (blockIdx.x & 1) * 64;
    const int tid  = threadIdx.x;
    const int lane = tid & 31;
    const int wid  = tid >> 5;

    __shared__ __align__(16) __nv_bfloat16 z1t_h[DH * 8];   // [d][h]
    __shared__ __align__(16) __nv_bfloat16 z1t_l[DH * 8];
    __shared__ __align__(16) __nv_bfloat16 z2t_h[64 * 8];   // [g_local][h]
    __shared__ __align__(16) __nv_bfloat16 z2t_l[64 * 8];
    __shared__ float hsm[DH];
    __shared__ float st_s[2][64], st_q[2][64];
    __shared__ float ysum[2][64];

    const float* base = g_scratch + (size_t)row * NCAT;

    // convert z1 (transposed [d][h]); thread tid <-> d
    {
        float zv[8];
        #pragma unroll
        for (int h = 0; h < 8; h++) zv[h] = base[256 + h * DH + tid];
        __nv_bfloat162 hp[4], lp[4];
        #pragma unroll
        for (int p = 0; p < 4; p++) {
            __nv_bfloat16 a = __float2bfloat16(zv[2*p]);
            __nv_bfloat16 b = __float2bfloat16(zv[2*p+1]);
            hp[p] = {a, b};
            lp[p] = {__float2bfloat16(zv[2*p]   - __bfloat162float(a)),
                     __float2bfloat16(zv[2*p+1] - __bfloat162float(b))};
        }
        *(int4*)(z1t_h + tid * 8) = *(int4*)hp;
        *(int4*)(z1t_l + tid * 8) = *(int4*)lp;
    }
    // convert z2 strip (transposed [g][h]); threads 0..63 <-> g local
    if (tid < 64) {
        const int g = g0 + tid;
        float zv[8];
        #pragma unroll
        for (int h = 0; h < 8; h++) zv[h] = base[2304 + h * DG + g];
        __nv_bfloat162 hp[4], lp[4];
        #pragma unroll
        for (int p = 0; p < 4; p++) {
            __nv_bfloat16 a = __float2bfloat16(zv[2*p]);
            __nv_bfloat16 b = __float2bfloat16(zv[2*p+1]);
            hp[p] = {a, b};
            lp[p] = {__float2bfloat16(zv[2*p]   - __bfloat162float(a)),
                     __float2bfloat16(zv[2*p+1] - __bfloat162float(b))};
        }
        *(int4*)(z2t_h + tid * 8) = *(int4*)hp;
        *(int4*)(z2t_l + tid * 8) = *(int4*)lp;
    }
    hsm[tid] = g_h[(size_t)row * DH + tid];
    __syncthreads();

    const int gstrip = (wid & 3) * 16;
    const int dhalf  = wid >> 2;
    const int d0     = dhalf * 128;

    const uint32_t uz1h = smem_u32(z1t_h), uz1l = smem_u32(z1t_l);
    const uint32_t uz2h = smem_u32(z2t_h), uz2l = smem_u32(z2t_l);

    // A fragments (z2^T strip, 16x8)
    uint32_t ah[2], al[2];
    {
        uint32_t aoff = (uint32_t)((gstrip + (lane & 15)) * 8) * 2u;
        LDSM_X2(ah[0], ah[1], uz2h + aoff);
        LDSM_X2(al[0], al[1], uz2l + aoff);
    }

    // MMA: 16 n-tiles of 8 d each, 3 split passes, K=8 single step
    float acc[16][4];
    #pragma unroll
    for (int t = 0; t < 16; t++)
        #pragma unroll
        for (int q = 0; q < 4; q++) acc[t][q] = 0.f;

    #pragma unroll
    for (int c = 0; c < 4; c++) {
        uint32_t boff = (uint32_t)((d0 + c * 32 + (lane >> 3) * 8 + (lane & 7)) * 8) * 2u;
        uint32_t bh4[4], bl4[4];
        LDSM_X4(bh4[0], bh4[1], bh4[2], bh4[3], uz1h + boff);
        LDSM_X4(bl4[0], bl4[1], bl4[2], bl4[3], uz1l + boff);
        #pragma unroll
        for (int t = 0; t < 4; t++) {
            MMA8(acc[c*4+t], ah, bh4[t]);
            MMA8(acc[c*4+t], ah, bl4[t]);
            MMA8(acc[c*4+t], al, bh4[t]);
        }
    }

    // stats: lane's c0,c1 -> g = gstrip + (lane>>2); c2,c3 -> +8
    float sA = 0.f, qA = 0.f, sB = 0.f, qB = 0.f;
    #pragma unroll
    for (int t = 0; t < 16; t++) {
        sA += acc[t][0] + acc[t][1];
        qA = fmaf(acc[t][0], acc[t][0], qA);
        qA = fmaf(acc[t][1], acc[t][1], qA);
        sB += acc[t][2] + acc[t][3];
        qB = fmaf(acc[t][2], acc[t][2], qB);
        qB = fmaf(acc[t][3], acc[t][3], qB);
    }
    #pragma unroll
    for (int o = 1; o <= 2; o <<= 1) {
        sA += __shfl_xor_sync(0xffffffffu, sA, o);
        qA += __shfl_xor_sync(0xffffffffu, qA, o);
        sB += __shfl_xor_sync(0xffffffffu, sB, o);
        qB += __shfl_xor_sync(0xffffffffu, qB, o);
    }
    const int glA = gstrip + (lane >> 2);
    const int glB = glA + 8;
    if ((lane & 3) == 0) {
        st_s[dhalf][glA] = sA;  st_q[dhalf][glA] = qA;
        st_s[dhalf][glB] = sB;  st_q[dhalf][glB] = qB;
    }
    __syncthreads();

    float alphaA, betaA, alphaB, betaB;
    {
        float s = st_s[0][glA] + st_s[1][glA];
        float q = st_q[0][glA] + st_q[1][glA];
        float mu = s * (1.f / 256.f);
        float var = fmaxf(q * (1.f / 256.f) - mu * mu, 0.f);
        alphaA = 1.f / (sqrtf(var) + 1e-6f);
        betaA = -mu * alphaA;
        s = st_s[0][glB] + st_s[1][glB];
        q = st_q[0][glB] + st_q[1][glB];
        mu = s * (1.f / 256.f);
        var = fmaxf(q * (1.f / 256.f) - mu * mu, 0.f);
        alphaB = 1.f / (sqrtf(var) + 1e-6f);
        betaB = -mu * alphaB;
    }

    // tanh + dot with h
    float yA = 0.f, yB = 0.f;
    #pragma unroll
    for (int t = 0; t < 16; t++) {
        const int d = d0 + t * 8 + 2 * (lane & 3);
        const float h0 = hsm[d], h1 = hsm[d + 1];
        yA = fmaf(tanh_fast(fmaf(acc[t][0], alphaA, betaA)), h0, yA);
        yA = fmaf(tanh_fast(fmaf(acc[t][1], alphaA, betaA)), h1, yA);
        yB = fmaf(tanh_fast(fmaf(acc[t][2], alphaB, betaB)), h0, yB);
        yB = fmaf(tanh_fast(fmaf(acc[t][3], alphaB, betaB)), h1, yB);
    }
    #pragma unroll
    for (int o = 1; o <= 2; o <<= 1) {
        yA += __shfl_xor_sync(0xffffffffu, yA, o);
        yB += __shfl_xor_sync(0xffffffffu, yB, o);
    }
    if ((lane & 3) == 0) {
        ysum[dhalf][glA] = yA;
        ysum[dhalf][glB] = yB;
    }
    __syncthreads();

    if (tid < 64) {
        out[(size_t)BROWS * DH + (size_t)row * DG + g0 + tid] =
            ysum[0][tid] + ysum[1][tid];
    }
}

// ---------------------------------------------------------------------------
extern "C" void kernel_launch(void* const* d_in, const int* in_sizes, int n_in,
                              void* d_out, int out_size)
{
    const float* x        = (const float*)d_in[0];
    const float* Wh       = (const float*)d_in[1];
    const float* bh       = (const float*)d_in[2];
    const float* Wz1      = (const float*)d_in[3];
    const float* Wz2      = (const float*)d_in[4];
    const float* ln_scale = (const float*)d_in[5];
    const float* ln_bias  = (const float*)d_in[6];
    float* out = (float*)d_out;

    convert_x_kernel<<<(BROWS * DIN) / (256 * 4), 256>>>(x);
    dim3 gw(NCAT / 32, DIN / 32);
    convert_w_kernel<<<gw, 1024>>>(Wh, Wz1, Wz2);

    dim3 gg(NCAT / 128, BROWS / 128);   // 26 x 32
    gemm_mma_kernel<<<gg, 256>>>();

    ln_kernel<<<BROWS, 256>>>(bh, ln_scale, ln_bias, out);
    fuse2_kernel<<<BROWS * 2, 256>>>(out);
}

// round 16
// speedup vs baseline: 1.0797x; 1.0797x over previous
#include <cuda_runtime.h>
#include <cuda_bf16.h>
#include <cstdint>

#define BROWS 4096
#define DIN   512
#define DH    256
#define DG    128
#define NHEAD 8
#define NCAT  3328   // 256 (h-branch) + 2048 (z1) + 1024 (z2)

__device__ float g_scratch[(size_t)BROWS * NCAT];
__device__ __nv_bfloat16 g_xh[(size_t)BROWS * DIN];
__device__ __nv_bfloat16 g_xl[(size_t)BROWS * DIN];
__device__ __nv_bfloat16 g_wth[(size_t)NCAT * DIN];
__device__ __nv_bfloat16 g_wtl[(size_t)NCAT * DIN];

__device__ __forceinline__ uint32_t smem_u32(const void* p) {
    uint32_t a;
    asm("{ .reg .u64 t; cvta.to.shared.u64 t, %1; cvt.u32.u64 %0, t; }" : "=r"(a) : "l"(p));
    return a;
}
__device__ __forceinline__ float tanh_fast(float x) {
    float r;
    asm("tanh.approx.f32 %0, %1;" : "=f"(r) : "f"(x));
    return r;
}

#define LDSM_X4(r0, r1, r2, r3, addr) \
    asm volatile("ldmatrix.sync.aligned.m8n8.x4.shared.b16 {%0,%1,%2,%3}, [%4];" \
                 : "=r"(r0), "=r"(r1), "=r"(r2), "=r"(r3) : "r"(addr))
#define LDSM_X2(r0, r1, addr) \
    asm volatile("ldmatrix.sync.aligned.m8n8.x2.shared.b16 {%0,%1}, [%2];" \
                 : "=r"(r0), "=r"(r1) : "r"(addr))

#define MMA_BF16(d, a, b) \
    asm volatile("mma.sync.aligned.m16n8k16.row.col.f32.bf16.bf16.f32 " \
                 "{%0,%1,%2,%3}, {%4,%5,%6,%7}, {%8,%9}, {%0,%1,%2,%3};" \
                 : "+f"((d)[0]), "+f"((d)[1]), "+f"((d)[2]), "+f"((d)[3]) \
                 : "r"((a)[0]), "r"((a)[1]), "r"((a)[2]), "r"((a)[3]), \
                   "r"((b)[0]), "r"((b)[1]))

#define MMA8(d, a, b) \
    asm volatile("mma.sync.aligned.m16n8k8.row.col.f32.bf16.bf16.f32 " \
                 "{%0,%1,%2,%3}, {%4,%5}, {%6}, {%0,%1,%2,%3};" \
                 : "+f"((d)[0]), "+f"((d)[1]), "+f"((d)[2]), "+f"((d)[3]) \
                 : "r"((a)[0]), "r"((a)[1]), "r"((b)))

#define CP_ASYNC16(smem, gptr) \
    asm volatile("cp.async.cg.shared.global [%0], [%1], 16;" :: "r"(smem), "l"(gptr))
#define CP_COMMIT() asm volatile("cp.async.commit_group;" ::: "memory")
#define CP_WAIT(n)  asm volatile("cp.async.wait_group %0;" :: "n"(n) : "memory")

// ---------------------------------------------------------------------------
// Convert X -> bf16 hi/lo
// ---------------------------------------------------------------------------
__global__ void convert_x_kernel(const float* __restrict__ X) {
    size_t i = ((size_t)blockIdx.x * blockDim.x + threadIdx.x) * 4;
    float4 v = *(const float4*)(X + i);
    __nv_bfloat16 h0 = __float2bfloat16(v.x), h1 = __float2bfloat16(v.y);
    __nv_bfloat16 h2 = __float2bfloat16(v.z), h3 = __float2bfloat16(v.w);
    __nv_bfloat162 hp0 = {h0, h1}, hp1 = {h2, h3};
    *(__nv_bfloat162*)(g_xh + i)     = hp0;
    *(__nv_bfloat162*)(g_xh + i + 2) = hp1;
    __nv_bfloat162 lp0 = {__float2bfloat16(v.x - __bfloat162float(h0)),
                          __float2bfloat16(v.y - __bfloat162float(h1))};
    __nv_bfloat162 lp1 = {__float2bfloat16(v.z - __bfloat162float(h2)),
                          __float2bfloat16(v.w - __bfloat162float(h3))};
    *(__nv_bfloat162*)(g_xl + i)     = lp0;
    *(__nv_bfloat162*)(g_xl + i + 2) = lp1;
}

// ---------------------------------------------------------------------------
// Transpose-convert [Wh|Wz1|Wz2] -> WT [3328, 512] bf16 hi/lo
// ---------------------------------------------------------------------------
__global__ __launch_bounds__(1024)
void convert_w_kernel(const float* __restrict__ Wh,
                      const float* __restrict__ Wz1,
                      const float* __restrict__ Wz2) {
    __shared__ float tile[32][33];
    const int n0 = blockIdx.x * 32;
    const int k0 = blockIdx.y * 32;
    const int tx = threadIdx.x & 31;
    const int ty = threadIdx.x >> 5;

    int n = n0 + tx, k = k0 + ty;
    float v;
    if (n < 256)       v = Wh [(size_t)k * 256  + n];
    else if (n < 2304) v = Wz1[(size_t)k * 2048 + (n - 256)];
    else               v = Wz2[(size_t)k * 1024 + (n - 2304)];
    tile[ty][tx] = v;
    __syncthreads();

    float w = tile[tx][ty];
    __nv_bfloat16 hi = __float2bfloat16(w);
    __nv_bfloat16 lo = __float2bfloat16(w - __bfloat162float(hi));
    size_t o = (size_t)(n0 + ty) * DIN + k0 + tx;
    g_wth[o] = hi;
    g_wtl[o] = lo;
}

// ---------------------------------------------------------------------------
// mma.sync bf16x3 GEMM with 2-stage cp.async pipeline.
// CTA tile 128x128, 8 warps, warp tile 64x32, K chunks of 32.
// Dynamic smem: 2 stages x 4 arrays x 128*KSTR bf16 = 80 KB.
// ---------------------------------------------------------------------------
#define KSTR 40
#define ARR_BYTES (128 * KSTR * 2)            // 10240
#define STAGE_BYTES (4 * ARR_BYTES)           // 40960
#define GEMM_SMEM (2 * STAGE_BYTES)           // 81920

__global__ __launch_bounds__(256, 2)
void gemm_mma_kernel() {
    extern __shared__ __align__(16) char dsm[];
    const uint32_t u0 = smem_u32(dsm);

    const int tid  = threadIdx.x;
    const int wid  = tid >> 5;
    const int lane = tid & 31;
    const int n0 = blockIdx.x * 128;
    const int m0 = blockIdx.y * 128;
    const int wm = wid & 1;
    const int wn = wid >> 1;

    const int grow = tid >> 1;
    const int gc   = (tid & 1) * 16;
    const size_t aoff = (size_t)(m0 + grow) * DIN + gc;
    const size_t boff = (size_t)(n0 + grow) * DIN + gc;
    const uint32_t soffB = (uint32_t)(grow * KSTR + gc) * 2u;   // bytes

    const int arow = wm * 64 + (lane & 15);
    const int acol = (lane >> 4) * 8;
    const int brow = wn * 32 + (lane & 7) + ((lane & 16) >> 1);
    const int bcol = (lane & 8);

    float acc[4][4][4];
    #pragma unroll
    for (int mi = 0; mi < 4; mi++)
        #pragma unroll
        for (int ni = 0; ni < 4; ni++)
            #pragma unroll
            for (int q = 0; q < 4; q++) acc[mi][ni][q] = 0.f;

    // prefetch helper (macro to keep addresses simple)
#define PREFETCH(stage, kc) do {                                              \
        const int kb_ = (kc) * 32;                                            \
        uint32_t s_ = u0 + (stage) * STAGE_BYTES + soffB;                     \
        CP_ASYNC16(s_,                     g_xh  + aoff + kb_);               \
        CP_ASYNC16(s_ + 16,                g_xh  + aoff + kb_ + 8);           \
        CP_ASYNC16(s_ + ARR_BYTES,         g_xl  + aoff + kb_);               \
        CP_ASYNC16(s_ + ARR_BYTES + 16,    g_xl  + aoff + kb_ + 8);           \
        CP_ASYNC16(s_ + 2*ARR_BYTES,       g_wth + boff + kb_);               \
        CP_ASYNC16(s_ + 2*ARR_BYTES + 16,  g_wth + boff + kb_ + 8);           \
        CP_ASYNC16(s_ + 3*ARR_BYTES,       g_wtl + boff + kb_);               \
        CP_ASYNC16(s_ + 3*ARR_BYTES + 16,  g_wtl + boff + kb_ + 8);           \
    } while (0)

    PREFETCH(0, 0);
    CP_COMMIT();

    #pragma unroll 1
    for (int kc = 0; kc < 16; kc++) {
        const int cur = kc & 1;
        if (kc < 15) {
            PREFETCH(cur ^ 1, kc + 1);
            CP_COMMIT();
            CP_WAIT(1);
        } else {
            CP_WAIT(0);
        }
        __syncthreads();

        const uint32_t uAh = u0 + cur * STAGE_BYTES;
        const uint32_t uAl = uAh + ARR_BYTES;
        const uint32_t uBh = uAh + 2 * ARR_BYTES;
        const uint32_t uBl = uAh + 3 * ARR_BYTES;

        #pragma unroll
        for (int ks = 0; ks < 2; ks++) {
            const int kk = ks * 16;
            uint32_t a[4][4], b1[4][2], b2[4][2];

            #pragma unroll
            for (int mi = 0; mi < 4; mi++) {
                uint32_t ad = uAh + 2u * (uint32_t)((arow + mi * 16) * KSTR + kk + acol);
                LDSM_X4(a[mi][0], a[mi][1], a[mi][2], a[mi][3], ad);
            }
            #pragma unroll
            for (int p = 0; p < 2; p++) {
                uint32_t bd = uBh + 2u * (uint32_t)((brow + p * 16) * KSTR + kk + bcol);
                LDSM_X4(b1[p*2][0], b1[p*2][1], b1[p*2+1][0], b1[p*2+1][1], bd);
            }
            #pragma unroll
            for (int mi = 0; mi < 4; mi++)
                #pragma unroll
                for (int ni = 0; ni < 4; ni++)
                    MMA_BF16(acc[mi][ni], a[mi], b1[ni]);

            #pragma unroll
            for (int p = 0; p < 2; p++) {
                uint32_t bd = uBl + 2u * (uint32_t)((brow + p * 16) * KSTR + kk + bcol);
                LDSM_X4(b2[p*2][0], b2[p*2][1], b2[p*2+1][0], b2[p*2+1][1], bd);
            }
            #pragma unroll
            for (int mi = 0; mi < 4; mi++)
                #pragma unroll
                for (int ni = 0; ni < 4; ni++)
                    MMA_BF16(acc[mi][ni], a[mi], b2[ni]);

            #pragma unroll
            for (int mi = 0; mi < 4; mi++) {
                uint32_t ad = uAl + 2u * (uint32_t)((arow + mi * 16) * KSTR + kk + acol);
                LDSM_X4(a[mi][0], a[mi][1], a[mi][2], a[mi][3], ad);
            }
            #pragma unroll
            for (int mi = 0; mi < 4; mi++)
                #pragma unroll
                for (int ni = 0; ni < 4; ni++)
                    MMA_BF16(acc[mi][ni], a[mi], b1[ni]);
        }
        __syncthreads();
    }
#undef PREFETCH

    const int erow = m0 + wm * 64 + (lane >> 2);
    const int ecol = n0 + wn * 32 + (lane & 3) * 2;
    #pragma unroll
    for (int mi = 0; mi < 4; mi++)
        #pragma unroll
        for (int ni = 0; ni < 4; ni++) {
            float* d0 = g_scratch + (size_t)(erow + mi * 16) * NCAT + ecol + ni * 8;
            float* d1 = d0 + 8 * NCAT;
            *(float2*)d0 = make_float2(acc[mi][ni][0], acc[mi][ni][1]);
            *(float2*)d1 = make_float2(acc[mi][ni][2], acc[mi][ni][3]);
        }
}

// ---------------------------------------------------------------------------
// fuse2: one block per row. LN folded in; z1 converted once; both g-halves
// processed sequentially. w = z2^T z1 via m16n8k8 bf16x3 HMMA.
// Warp layout per half: 8 warps = 4 g-strips (16 g) x 2 d-halves (128 d).
// ---------------------------------------------------------------------------
__global__ __launch_bounds__(256, 2)
void fuse2_kernel(const float* __restrict__ bh,
                  const float* __restrict__ ln_scale,
                  const float* __restrict__ ln_bias,
                  float* __restrict__ out)
{
    const int row  = blockIdx.x;
    const int tid  = threadIdx.x;
    const int lane = tid & 31;
    const int wid  = tid >> 5;

    __shared__ __align__(16) __nv_bfloat16 z1t_h[DH * 8];   // [d][h]
    __shared__ __align__(16) __nv_bfloat16 z1t_l[DH * 8];
    __shared__ __align__(16) __nv_bfloat16 z2t_h[DG * 8];   // [g][h]
    __shared__ __align__(16) __nv_bfloat16 z2t_l[DG * 8];
    __shared__ float hsm[DH];
    __shared__ float red[2][8];
    __shared__ float st_s[2][64], st_q[2][64];
    __shared__ float ysum[2][64];

    const float* base = g_scratch + (size_t)row * NCAT;

    // ---- LN branch: h = LN(relu(a + bh)) ----
    {
        float v = fmaxf(base[tid] + bh[tid], 0.f);
        float s = v, q = v * v;
        #pragma unroll
        for (int o = 16; o; o >>= 1) {
            s += __shfl_xor_sync(0xffffffffu, s, o);
            q += __shfl_xor_sync(0xffffffffu, q, o);
        }
        if (lane == 0) { red[0][wid] = s; red[1][wid] = q; }
        __syncthreads();
        float ts = 0.f, tq = 0.f;
        #pragma unroll
        for (int i = 0; i < 8; i++) { ts += red[0][i]; tq += red[1][i]; }
        const float mu  = ts * (1.f / 256.f);
        const float var = tq * (1.f / 256.f) - mu * mu;
        const float inv = rsqrtf(var + 1e-6f);
        const float hv  = (v - mu) * inv * ln_scale[tid] + ln_bias[tid];
        out[(size_t)row * DH + tid] = hv;
        hsm[tid] = hv;
    }

    // ---- convert z1 (transposed [d][h]); thread tid <-> d ----
    {
        float zv[8];
        #pragma unroll
        for (int h = 0; h < 8; h++) zv[h] = base[256 + h * DH + tid];
        __nv_bfloat162 hp[4], lp[4];
        #pragma unroll
        for (int p = 0; p < 4; p++) {
            __nv_bfloat16 a = __float2bfloat16(zv[2*p]);
            __nv_bfloat16 b = __float2bfloat16(zv[2*p+1]);
            hp[p] = {a, b};
            lp[p] = {__float2bfloat16(zv[2*p]   - __bfloat162float(a)),
                     __float2bfloat16(zv[2*p+1] - __bfloat162float(b))};
        }
        *(int4*)(z1t_h + tid * 8) = *(int4*)hp;
        *(int4*)(z1t_l + tid * 8) = *(int4*)lp;
    }
    // ---- convert z2 (transposed [g][h]); threads 0..127 <-> g ----
    if (tid < DG) {
        float zv[8];
        #pragma unroll
        for (int h = 0; h < 8; h++) zv[h] = base[2304 + h * DG + tid];
        __nv_bfloat162 hp[4], lp[4];
        #pragma unroll
        for (int p = 0; p < 4; p++) {
            __nv_bfloat16 a = __float2bfloat16(zv[2*p]);
            __nv_bfloat16 b = __float2bfloat16(zv[2*p+1]);
            hp[p] = {a, b};
            lp[p] = {__float2bfloat16(zv[2*p]   - __bfloat162float(a)),
                     __float2bfloat16(zv[2*p+1] - __bfloat162float(b))};
        }
        *(int4*)(z2t_h + tid * 8) = *(int4*)hp;
        *(int4*)(z2t_l + tid * 8) = *(int4*)lp;
    }
    __syncthreads();

    const int gstrip = (wid & 3) * 16;
    const int dhalf  = wid >> 2;
    const int d0     = dhalf * 128;

    const uint32_t uz1h = smem_u32(z1t_h), uz1l = smem_u32(z1t_l);
    const uint32_t uz2h = smem_u32(z2t_h), uz2l = smem_u32(z2t_l);

    float* out_y = out + (size_t)BROWS * DH + (size_t)row * DG;

    #pragma unroll 1
    for (int half = 0; half < 2; half++) {
        const int g0 = half * 64;

        // A fragments (z2^T strip, 16x8)
        uint32_t ah[2], al[2];
        {
            uint32_t aoff = (uint32_t)((g0 + gstrip + (lane & 15)) * 8) * 2u;
            LDSM_X2(ah[0], ah[1], uz2h + aoff);
            LDSM_X2(al[0], al[1], uz2l + aoff);
        }

        float acc[16][4];
        #pragma unroll
        for (int t = 0; t < 16; t++)
            #pragma unroll
            for (int q = 0; q < 4; q++) acc[t][q] = 0.f;

        #pragma unroll
        for (int c = 0; c < 4; c++) {
            uint32_t boff = (uint32_t)((d0 + c * 32 + (lane >> 3) * 8 + (lane & 7)) * 8) * 2u;
            uint32_t bh4[4], bl4[4];
            LDSM_X4(bh4[0], bh4[1], bh4[2], bh4[3], uz1h + boff);
            LDSM_X4(bl4[0], bl4[1], bl4[2], bl4[3], uz1l + boff);
            #pragma unroll
            for (int t = 0; t < 4; t++) {
                MMA8(acc[c*4+t], ah, bh4[t]);
                MMA8(acc[c*4+t], ah, bl4[t]);
                MMA8(acc[c*4+t], al, bh4[t]);
            }
        }

        // stats: lane's c0,c1 -> g = gstrip + (lane>>2); c2,c3 -> +8
        float sA = 0.f, qA = 0.f, sB = 0.f, qB = 0.f;
        #pragma unroll
        for (int t = 0; t < 16; t++) {
            sA += acc[t][0] + acc[t][1];
            qA = fmaf(acc[t][0], acc[t][0], qA);
            qA = fmaf(acc[t][1], acc[t][1], qA);
            sB += acc[t][2] + acc[t][3];
            qB = fmaf(acc[t][2], acc[t][2], qB);
            qB = fmaf(acc[t][3], acc[t][3], qB);
        }
        #pragma unroll
        for (int o = 1; o <= 2; o <<= 1) {
            sA += __shfl_xor_sync(0xffffffffu, sA, o);
            qA += __shfl_xor_sync(0xffffffffu, qA, o);
            sB += __shfl_xor_sync(0xffffffffu, sB, o);
            qB += __shfl_xor_sync(0xffffffffu, qB, o);
        }
        const int glA = gstrip + (lane >> 2);
        const int glB = glA + 8;
        if ((lane & 3) == 0) {
            st_s[dhalf][glA] = sA;  st_q[dhalf][glA] = qA;
            st_s[dhalf][glB] = sB;  st_q[dhalf][glB] = qB;
        }
        __syncthreads();

        float alphaA, betaA, alphaB, betaB;
        {
            float s = st_s[0][glA] + st_s[1][glA];
            float q = st_q[0][glA] + st_q[1][glA];
            float mu = s * (1.f / 256.f);
            float var = fmaxf(q * (1.f / 256.f) - mu * mu, 0.f);
            alphaA = 1.f / (sqrtf(var) + 1e-6f);
            betaA = -mu * alphaA;
            s = st_s[0][glB] + st_s[1][glB];
            q = st_q[0][glB] + st_q[1][glB];
            mu = s * (1.f / 256.f);
            var = fmaxf(q * (1.f / 256.f) - mu * mu, 0.f);
            alphaB = 1.f / (sqrtf(var) + 1e-6f);
            betaB = -mu * alphaB;
        }

        // tanh + dot with h
        float yA = 0.f, yB = 0.f;
        #pragma unroll
        for (int t = 0; t < 16; t++) {
            const int d = d0 + t * 8 + 2 * (lane & 3);
            const float h0 = hsm[d], h1 = hsm[d + 1];
            yA = fmaf(tanh_fast(fmaf(acc[t][0], alphaA, betaA)), h0, yA);
            yA = fmaf(tanh_fast(fmaf(acc[t][1], alphaA, betaA)), h1, yA);
            yB = fmaf(tanh_fast(fmaf(acc[t][2], alphaB, betaB)), h0, yB);
            yB = fmaf(tanh_fast(fmaf(acc[t][3], alphaB, betaB)), h1, yB);
        }
        #pragma unroll
        for (int o = 1; o <= 2; o <<= 1) {
            yA += __shfl_xor_sync(0xffffffffu, yA, o);
            yB += __shfl_xor_sync(0xffffffffu, yB, o);
        }
        if ((lane & 3) == 0) {
            ysum[dhalf][glA] = yA;
            ysum[dhalf][glB] = yB;
        }
        __syncthreads();

        if (tid < 64)
            out_y[g0 + tid] = ysum[0][tid] + ysum[1][tid];
    }
}

// ---------------------------------------------------------------------------
extern "C" void kernel_launch(void* const* d_in, const int* in_sizes, int n_in,
                              void* d_out, int out_size)
{
    const float* x        = (const float*)d_in[0];
    const float* Wh       = (const float*)d_in[1];
    const float* bh       = (const float*)d_in[2];
    const float* Wz1      = (const float*)d_in[3];
    const float* Wz2      = (const float*)d_in[4];
    const float* ln_scale = (const float*)d_in[5];
    const float* ln_bias  = (const float*)d_in[6];
    float* out = (float*)d_out;

    static bool attr_set = false;
    if (!attr_set) {
        cudaFuncSetAttribute(gemm_mma_kernel,
                             cudaFuncAttributeMaxDynamicSharedMemorySize, GEMM_SMEM);
        attr_set = true;
    }

    convert_x_kernel<<<(BROWS * DIN) / (256 * 4), 256>>>(x);
    dim3 gw(NCAT / 32, DIN / 32);
    convert_w_kernel<<<gw, 1024>>>(Wh, Wz1, Wz2);

    dim3 gg(NCAT / 128, BROWS / 128);   // 26 x 32
    gemm_mma_kernel<<<gg, 256, GEMM_SMEM>>>();

    fuse2_kernel<<<BROWS, 256>>>(bh, ln_scale, ln_bias, out);
}

// round 17
// speedup vs baseline: 1.0801x; 1.0004x over previous
#include <cuda_runtime.h>
#include <cuda_bf16.h>
#include <cstdint>

#define BROWS 4096
#define DIN   512
#define DH    256
#define DG    128
#define NHEAD 8
#define NCAT  3328   // 256 (h-branch) + 2048 (z1) + 1024 (z2)

__device__ float g_scratch[(size_t)BROWS * NCAT];
__device__ __nv_bfloat16 g_xh[(size_t)BROWS * DIN];
__device__ __nv_bfloat16 g_xl[(size_t)BROWS * DIN];
__device__ __nv_bfloat16 g_wth[(size_t)NCAT * DIN];
__device__ __nv_bfloat16 g_wtl[(size_t)NCAT * DIN];

__device__ __forceinline__ uint32_t smem_u32(const void* p) {
    uint32_t a;
    asm("{ .reg .u64 t; cvta.to.shared.u64 t, %1; cvt.u32.u64 %0, t; }" : "=r"(a) : "l"(p));
    return a;
}
__device__ __forceinline__ float tanh_fast(float x) {
    float r;
    asm("tanh.approx.f32 %0, %1;" : "=f"(r) : "f"(x));
    return r;
}

#define LDSM_X4(r0, r1, r2, r3, addr) \
    asm volatile("ldmatrix.sync.aligned.m8n8.x4.shared.b16 {%0,%1,%2,%3}, [%4];" \
                 : "=r"(r0), "=r"(r1), "=r"(r2), "=r"(r3) : "r"(addr))
#define LDSM_X2(r0, r1, addr) \
    asm volatile("ldmatrix.sync.aligned.m8n8.x2.shared.b16 {%0,%1}, [%2];" \
                 : "=r"(r0), "=r"(r1) : "r"(addr))

#define MMA_BF16(d, a, b) \
    asm volatile("mma.sync.aligned.m16n8k16.row.col.f32.bf16.bf16.f32 " \
                 "{%0,%1,%2,%3}, {%4,%5,%6,%7}, {%8,%9}, {%0,%1,%2,%3};" \
                 : "+f"((d)[0]), "+f"((d)[1]), "+f"((d)[2]), "+f"((d)[3]) \
                 : "r"((a)[0]), "r"((a)[1]), "r"((a)[2]), "r"((a)[3]), \
                   "r"((b)[0]), "r"((b)[1]))

#define MMA8(d, a, b) \
    asm volatile("mma.sync.aligned.m16n8k8.row.col.f32.bf16.bf16.f32 " \
                 "{%0,%1,%2,%3}, {%4,%5}, {%6}, {%0,%1,%2,%3};" \
                 : "+f"((d)[0]), "+f"((d)[1]), "+f"((d)[2]), "+f"((d)[3]) \
                 : "r"((a)[0]), "r"((a)[1]), "r"((b)))

#define CP_ASYNC16(smem, gptr) \
    asm volatile("cp.async.cg.shared.global [%0], [%1], 16;" :: "r"(smem), "l"(gptr))
#define CP_COMMIT() asm volatile("cp.async.commit_group;" ::: "memory")
#define CP_WAIT(n)  asm volatile("cp.async.wait_group %0;" :: "n"(n) : "memory")

// ---------------------------------------------------------------------------
// Convert X -> bf16 hi/lo
// ---------------------------------------------------------------------------
__global__ void convert_x_kernel(const float* __restrict__ X) {
    size_t i = ((size_t)blockIdx.x * blockDim.x + threadIdx.x) * 4;
    float4 v = *(const float4*)(X + i);
    __nv_bfloat16 h0 = __float2bfloat16(v.x), h1 = __float2bfloat16(v.y);
    __nv_bfloat16 h2 = __float2bfloat16(v.z), h3 = __float2bfloat16(v.w);
    __nv_bfloat162 hp0 = {h0, h1}, hp1 = {h2, h3};
    *(__nv_bfloat162*)(g_xh + i)     = hp0;
    *(__nv_bfloat162*)(g_xh + i + 2) = hp1;
    __nv_bfloat162 lp0 = {__float2bfloat16(v.x - __bfloat162float(h0)),
                          __float2bfloat16(v.y - __bfloat162float(h1))};
    __nv_bfloat162 lp1 = {__float2bfloat16(v.z - __bfloat162float(h2)),
                          __float2bfloat16(v.w - __bfloat162float(h3))};
    *(__nv_bfloat162*)(g_xl + i)     = lp0;
    *(__nv_bfloat162*)(g_xl + i + 2) = lp1;
}

// ---------------------------------------------------------------------------
// Transpose-convert [Wh|Wz1|Wz2] -> WT [3328, 512] bf16 hi/lo
// ---------------------------------------------------------------------------
__global__ __launch_bounds__(1024)
void convert_w_kernel(const float* __restrict__ Wh,
                      const float* __restrict__ Wz1,
                      const float* __restrict__ Wz2) {
    __shared__ float tile[32][33];
    const int n0 = blockIdx.x * 32;
    const int k0 = blockIdx.y * 32;
    const int tx = threadIdx.x & 31;
    const int ty = threadIdx.x >> 5;

    int n = n0 + tx, k = k0 + ty;
    float v;
    if (n < 256)       v = Wh [(size_t)k * 256  + n];
    else if (n < 2304) v = Wz1[(size_t)k * 2048 + (n - 256)];
    else               v = Wz2[(size_t)k * 1024 + (n - 2304)];
    tile[ty][tx] = v;
    __syncthreads();

    float w = tile[tx][ty];
    __nv_bfloat16 hi = __float2bfloat16(w);
    __nv_bfloat16 lo = __float2bfloat16(w - __bfloat162float(hi));
    size_t o = (size_t)(n0 + ty) * DIN + k0 + tx;
    g_wth[o] = hi;
    g_wtl[o] = lo;
}

// ---------------------------------------------------------------------------
// mma.sync bf16x3 GEMM with 2-stage cp.async pipeline.
// CTA tile 128x128, 8 warps, warp tile 64x32, K chunks of 32.
// Dynamic smem: 2 stages x 4 arrays x 128*KSTR bf16 = 80 KB.
// ---------------------------------------------------------------------------
#define KSTR 40
#define ARR_BYTES (128 * KSTR * 2)            // 10240
#define STAGE_BYTES (4 * ARR_BYTES)           // 40960
#define GEMM_SMEM (2 * STAGE_BYTES)           // 81920

__global__ __launch_bounds__(256, 2)
void gemm_mma_kernel() {
    extern __shared__ __align__(16) char dsm[];
    const uint32_t u0 = smem_u32(dsm);

    const int tid  = threadIdx.x;
    const int wid  = tid >> 5;
    const int lane = tid & 31;
    const int n0 = blockIdx.x * 128;
    const int m0 = blockIdx.y * 128;
    const int wm = wid & 1;
    const int wn = wid >> 1;

    const int grow = tid >> 1;
    const int gc   = (tid & 1) * 16;
    const size_t aoff = (size_t)(m0 + grow) * DIN + gc;
    const size_t boff = (size_t)(n0 + grow) * DIN + gc;
    const uint32_t soffB = (uint32_t)(grow * KSTR + gc) * 2u;   // bytes

    const int arow = wm * 64 + (lane & 15);
    const int acol = (lane >> 4) * 8;
    const int brow = wn * 32 + (lane & 7) + ((lane & 16) >> 1);
    const int bcol = (lane & 8);

    float acc[4][4][4];
    #pragma unroll
    for (int mi = 0; mi < 4; mi++)
        #pragma unroll
        for (int ni = 0; ni < 4; ni++)
            #pragma unroll
            for (int q = 0; q < 4; q++) acc[mi][ni][q] = 0.f;

    // prefetch helper (macro to keep addresses simple)
#define PREFETCH(stage, kc) do {                                              \
        const int kb_ = (kc) * 32;                                            \
        uint32_t s_ = u0 + (stage) * STAGE_BYTES + soffB;                     \
        CP_ASYNC16(s_,                     g_xh  + aoff + kb_);               \
        CP_ASYNC16(s_ + 16,                g_xh  + aoff + kb_ + 8);           \
        CP_ASYNC16(s_ + ARR_BYTES,         g_xl  + aoff + kb_);               \
        CP_ASYNC16(s_ + ARR_BYTES + 16,    g_xl  + aoff + kb_ + 8);           \
        CP_ASYNC16(s_ + 2*ARR_BYTES,       g_wth + boff + kb_);               \
        CP_ASYNC16(s_ + 2*ARR_BYTES + 16,  g_wth + boff + kb_ + 8);           \
        CP_ASYNC16(s_ + 3*ARR_BYTES,       g_wtl + boff + kb_);               \
        CP_ASYNC16(s_ + 3*ARR_BYTES + 16,  g_wtl + boff + kb_ + 8);           \
    } while (0)

    PREFETCH(0, 0);
    CP_COMMIT();

    #pragma unroll 1
    for (int kc = 0; kc < 16; kc++) {
        const int cur = kc & 1;
        if (kc < 15) {
            PREFETCH(cur ^ 1, kc + 1);
            CP_COMMIT();
            CP_WAIT(1);
        } else {
            CP_WAIT(0);
        }
        __syncthreads();

        const uint32_t uAh = u0 + cur * STAGE_BYTES;
        const uint32_t uAl = uAh + ARR_BYTES;
        const uint32_t uBh = uAh + 2 * ARR_BYTES;
        const uint32_t uBl = uAh + 3 * ARR_BYTES;

        #pragma unroll
        for (int ks = 0; ks < 2; ks++) {
            const int kk = ks * 16;
            uint32_t a[4][4], b1[4][2], b2[4][2];

            #pragma unroll
            for (int mi = 0; mi < 4; mi++) {
                uint32_t ad = uAh + 2u * (uint32_t)((arow + mi * 16) * KSTR + kk + acol);
                LDSM_X4(a[mi][0], a[mi][1], a[mi][2], a[mi][3], ad);
            }
            #pragma unroll
            for (int p = 0; p < 2; p++) {
                uint32_t bd = uBh + 2u * (uint32_t)((brow + p * 16) * KSTR + kk + bcol);
                LDSM_X4(b1[p*2][0], b1[p*2][1], b1[p*2+1][0], b1[p*2+1][1], bd);
            }
            #pragma unroll
            for (int mi = 0; mi < 4; mi++)
                #pragma unroll
                for (int ni = 0; ni < 4; ni++)
                    MMA_BF16(acc[mi][ni], a[mi], b1[ni]);

            #pragma unroll
            for (int p = 0; p < 2; p++) {
                uint32_t bd = uBl + 2u * (uint32_t)((brow + p * 16) * KSTR + kk + bcol);
                LDSM_X4(b2[p*2][0], b2[p*2][1], b2[p*2+1][0], b2[p*2+1][1], bd);
            }
            #pragma unroll
            for (int mi = 0; mi < 4; mi++)
                #pragma unroll
                for (int ni = 0; ni < 4; ni++)
                    MMA_BF16(acc[mi][ni], a[mi], b2[ni]);

            #pragma unroll
            for (int mi = 0; mi < 4; mi++) {
                uint32_t ad = uAl + 2u * (uint32_t)((arow + mi * 16) * KSTR + kk + acol);
                LDSM_X4(a[mi][0], a[mi][1], a[mi][2], a[mi][3], ad);
            }
            #pragma unroll
            for (int mi = 0; mi < 4; mi++)
                #pragma unroll
                for (int ni = 0; ni < 4; ni++)
                    MMA_BF16(acc[mi][ni], a[mi], b1[ni]);
        }
        __syncthreads();
    }
#undef PREFETCH

    const int erow = m0 + wm * 64 + (lane >> 2);
    const int ecol = n0 + wn * 32 + (lane & 3) * 2;
    #pragma unroll
    for (int mi = 0; mi < 4; mi++)
        #pragma unroll
        for (int ni = 0; ni < 4; ni++) {
            float* d0 = g_scratch + (size_t)(erow + mi * 16) * NCAT + ecol + ni * 8;
            float* d1 = d0 + 8 * NCAT;
            *(float2*)d0 = make_float2(acc[mi][ni][0], acc[mi][ni][1]);
            *(float2*)d1 = make_float2(acc[mi][ni][2], acc[mi][ni][3]);
        }
}

// ---------------------------------------------------------------------------
// fuse2: one block per row. LN folded in; z1 converted once; both g-halves
// processed sequentially. w = z2^T z1 via m16n8k8 bf16x3 HMMA.
// Warp layout per half: 8 warps = 4 g-strips (16 g) x 2 d-halves (128 d).
// ---------------------------------------------------------------------------
__global__ __launch_bounds__(256, 2)
void fuse2_kernel(const float* __restrict__ bh,
                  const float* __restrict__ ln_scale,
                  const float* __restrict__ ln_bias,
                  float* __restrict__ out)
{
    const int row  = blockIdx.x;
    const int tid  = threadIdx.x;
    const int lane = tid & 31;
    const int wid  = tid >> 5;

    __shared__ __align__(16) __nv_bfloat16 z1t_h[DH * 8];   // [d][h]
    __shared__ __align__(16) __nv_bfloat16 z1t_l[DH * 8];
    __shared__ __align__(16) __nv_bfloat16 z2t_h[DG * 8];   // [g][h]
    __shared__ __align__(16) __nv_bfloat16 z2t_l[DG * 8];
    __shared__ float hsm[DH];
    __shared__ float red[2][8];
    __shared__ float st_s[2][64], st_q[2][64];
    __shared__ float ysum[2][64];

    const float* base = g_scratch + (size_t)row * NCAT;

    // ---- LN branch: h = LN(relu(a + bh)) ----
    {
        float v = fmaxf(base[tid] + bh[tid], 0.f);
        float s = v, q = v * v;
        #pragma unroll
        for (int o = 16; o; o >>= 1) {
            s += __shfl_xor_sync(0xffffffffu, s, o);
            q += __shfl_xor_sync(0xffffffffu, q, o);
        }
        if (lane == 0) { red[0][wid] = s; red[1][wid] = q; }
        __syncthreads();
        float ts = 0.f, tq = 0.f;
        #pragma unroll
        for (int i = 0; i < 8; i++) { ts += red[0][i]; tq += red[1][i]; }
        const float mu  = ts * (1.f / 256.f);
        const float var = tq * (1.f / 256.f) - mu * mu;
        const float inv = rsqrtf(var + 1e-6f);
        const float hv  = (v - mu) * inv * ln_scale[tid] + ln_bias[tid];
        out[(size_t)row * DH + tid] = hv;
        hsm[tid] = hv;
    }

    // ---- convert z1 (transposed [d][h]); thread tid <-> d ----
    {
        float zv[8];
        #pragma unroll
        for (int h = 0; h < 8; h++) zv[h] = base[256 + h * DH + tid];
        __nv_bfloat162 hp[4], lp[4];
        #pragma unroll
        for (int p = 0; p < 4; p++) {
            __nv_bfloat16 a = __float2bfloat16(zv[2*p]);
            __nv_bfloat16 b = __float2bfloat16(zv[2*p+1]);
            hp[p] = {a, b};
            lp[p] = {__float2bfloat16(zv[2*p]   - __bfloat162float(a)),
                     __float2bfloat16(zv[2*p+1] - __bfloat162float(b))};
        }
        *(int4*)(z1t_h + tid * 8) = *(int4*)hp;
        *(int4*)(z1t_l + tid * 8) = *(int4*)lp;
    }
    // ---- convert z2 (transposed [g][h]); threads 0..127 <-> g ----
    if (tid < DG) {
        float zv[8];
        #pragma unroll
        for (int h = 0; h < 8; h++) zv[h] = base[2304 + h * DG + tid];
        __nv_bfloat162 hp[4], lp[4];
        #pragma unroll
        for (int p = 0; p < 4; p++) {
            __nv_bfloat16 a = __float2bfloat16(zv[2*p]);
            __nv_bfloat16 b = __float2bfloat16(zv[2*p+1]);
            hp[p] = {a, b};
            lp[p] = {__float2bfloat16(zv[2*p]   - __bfloat162float(a)),
                     __float2bfloat16(zv[2*p+1] - __bfloat162float(b))};
        }
        *(int4*)(z2t_h + tid * 8) = *(int4*)hp;
        *(int4*)(z2t_l + tid * 8) = *(int4*)lp;
    }
    __syncthreads();

    const int gstrip = (wid & 3) * 16;
    const int dhalf  = wid >> 2;
    const int d0     = dhalf * 128;

    const uint32_t uz1h = smem_u32(z1t_h), uz1l = smem_u32(z1t_l);
    const uint32_t uz2h = smem_u32(z2t_h), uz2l = smem_u32(z2t_l);

    float* out_y = out + (size_t)BROWS * DH + (size_t)row * DG;

    #pragma unroll 1
    for (int half = 0; half < 2; half++) {
        const int g0 = half * 64;

        // A fragments (z2^T strip, 16x8)
        uint32_t ah[2], al[2];
        {
            uint32_t aoff = (uint32_t)((g0 + gstrip + (lane & 15)) * 8) * 2u;
            LDSM_X2(ah[0], ah[1], uz2h + aoff);
            LDSM_X2(al[0], al[1], uz2l + aoff);
        }

        float acc[16][4];
        #pragma unroll
        for (int t = 0; t < 16; t++)
            #pragma unroll
            for (int q = 0; q < 4; q++) acc[t][q] = 0.f;

        #pragma unroll
        for (int c = 0; c < 4; c++) {
            uint32_t boff = (uint32_t)((d0 + c * 32 + (lane >> 3) * 8 + (lane & 7)) * 8) * 2u;
            uint32_t bh4[4], bl4[4];
            LDSM_X4(bh4[0], bh4[1], bh4[2], bh4[3], uz1h + boff);
            LDSM_X4(bl4[0], bl4[1], bl4[2], bl4[3], uz1l + boff);
            #pragma unroll
            for (int t = 0; t < 4; t++) {
                MMA8(acc[c*4+t], ah, bh4[t]);
                MMA8(acc[c*4+t], ah, bl4[t]);
                MMA8(acc[c*4+t], al, bh4[t]);
            }
        }

        // stats: lane's c0,c1 -> g = gstrip + (lane>>2); c2,c3 -> +8
        float sA = 0.f, qA = 0.f, sB = 0.f, qB = 0.f;
        #pragma unroll
        for (int t = 0; t < 16; t++) {
            sA += acc[t][0] + acc[t][1];
            qA = fmaf(acc[t][0], acc[t][0], qA);
            qA = fmaf(acc[t][1], acc[t][1], qA);
            sB += acc[t][2] + acc[t][3];
            qB = fmaf(acc[t][2], acc[t][2], qB);
            qB = fmaf(acc[t][3], acc[t][3], qB);
        }
        #pragma unroll
        for (int o = 1; o <= 2; o <<= 1) {
            sA += __shfl_xor_sync(0xffffffffu, sA, o);
            qA += __shfl_xor_sync(0xffffffffu, qA, o);
            sB += __shfl_xor_sync(0xffffffffu, sB, o);
            qB += __shfl_xor_sync(0xffffffffu, qB, o);
        }
        const int glA = gstrip + (lane >> 2);
        const int glB = glA + 8;
        if ((lane & 3) == 0) {
            st_s[dhalf][glA] = sA;  st_q[dhalf][glA] = qA;
            st_s[dhalf][glB] = sB;  st_q[dhalf][glB] = qB;
        }
        __syncthreads();

        float alphaA, betaA, alphaB, betaB;
        {
            float s = st_s[0][glA] + st_s[1][glA];
            float q = st_q[0][glA] + st_q[1][glA];
            float mu = s * (1.f / 256.f);
            float var = fmaxf(q * (1.f / 256.f) - mu * mu, 0.f);
            alphaA = 1.f / (sqrtf(var) + 1e-6f);
            betaA = -mu * alphaA;
            s = st_s[0][glB] + st_s[1][glB];
            q = st_q[0][glB] + st_q[1][glB];
            mu = s * (1.f / 256.f);
            var = fmaxf(q * (1.f / 256.f) - mu * mu, 0.f);
            alphaB = 1.f / (sqrtf(var) + 1e-6f);
            betaB = -mu * alphaB;
        }

        // tanh + dot with h
        float yA = 0.f, yB = 0.f;
        #pragma unroll
        for (int t = 0; t < 16; t++) {
            const int d = d0 + t * 8 + 2 * (lane & 3);
            const float h0 = hsm[d], h1 = hsm[d + 1];
            yA = fmaf(tanh_fast(fmaf(acc[t][0], alphaA, betaA)), h0, yA);
            yA = fmaf(tanh_fast(fmaf(acc[t][1], alphaA, betaA)), h1, yA);
            yB = fmaf(tanh_fast(fmaf(acc[t][2], alphaB, betaB)), h0, yB);
            yB = fmaf(tanh_fast(fmaf(acc[t][3], alphaB, betaB)), h1, yB);
        }
        #pragma unroll
        for (int o = 1; o <= 2; o <<= 1) {
            yA += __shfl_xor_sync(0xffffffffu, yA, o);
            yB += __shfl_xor_sync(0xffffffffu, yB, o);
        }
        if ((lane & 3) == 0) {
            ysum[dhalf][glA] = yA;
            ysum[dhalf][glB] = yB;
        }
        __syncthreads();

        if (tid < 64)
            out_y[g0 + tid] = ysum[0][tid] + ysum[1][tid];
    }
}

// ---------------------------------------------------------------------------
extern "C" void kernel_launch(void* const* d_in, const int* in_sizes, int n_in,
                              void* d_out, int out_size)
{
    const float* x        = (const float*)d_in[0];
    const float* Wh       = (const float*)d_in[1];
    const float* bh       = (const float*)d_in[2];
    const float* Wz1      = (const float*)d_in[3];
    const float* Wz2      = (const float*)d_in[4];
    const float* ln_scale = (const float*)d_in[5];
    const float* ln_bias  = (const float*)d_in[6];
    float* out = (float*)d_out;

    static bool attr_set = false;
    if (!attr_set) {
        cudaFuncSetAttribute(gemm_mma_kernel,
                             cudaFuncAttributeMaxDynamicSharedMemorySize, GEMM_SMEM);
        attr_set = true;
    }

    convert_x_kernel<<<(BROWS * DIN) / (256 * 4), 256>>>(x);
    dim3 gw(NCAT / 32, DIN / 32);
    convert_w_kernel<<<gw, 1024>>>(Wh, Wz1, Wz2);

    dim3 gg(NCAT / 128, BROWS / 128);   // 26 x 32
    gemm_mma_kernel<<<gg, 256, GEMM_SMEM>>>();

    fuse2_kernel<<<BROWS, 256>>>(bh, ln_scale, ln_bias, out);
}